// round 4
// baseline (speedup 1.0000x reference)
#include <cuda_runtime.h>

// GRU_83906481094863 — fused persistent GRU on sm_100a, v3 (latency-hiding).
// B=512, T=1024, D=46, H=128. 128 CTAs x 320 threads, NB=4 batches/CTA.
// 8 gate warps (2 per SMSP): warp w owns hidden units u = w*16 + (lane&15);
//   lanes 0-15 accumulate k in [0,64), lanes 16-31 k in [64,128) (h read from a
//   bank-offset replica to stay conflict-free). Partials combined with
//   __shfl_down(...,16); lanes 0-15 apply the gate nonlinearities in register
//   and store h' (main + replica). W_hh in shared (k-chunk-major LDS.128),
//   W_ih half-rows in registers, all MACs via packed fma.rn.f32x2.
// threads [256,320): aux, prefetch x(t+1). ONE __syncthreads per step.

#define BB 512
#define TT 1024
#define DD 46
#define DP 48
#define HH 128
#define GG 384
#define NB 4
#define NCTA (BB/NB)   // 128
#define NTHR 320
#define NGATE 256

// Shared layout (floats):
//  sW   [0, 49152)        W_hh k-chunk-major: float4 idx (kc*GG + j)
//  sH   [49152, 50176)    h main double buffer [2][NB][HH]
//  sHr  [50192, 50704)    h replica [2][NB][64] of h[64:128)  (base ≡ +16 banks)
//  sX   [50704, 51088)    x double buffer [2][NB][DP]
#define OFF_H   49152
#define OFF_HR  50192
#define OFF_X   50704
#define SMEM_FLOATS 51088
#define SMEM_BYTES  (SMEM_FLOATS * 4)

__device__ __forceinline__ void fma2(unsigned long long &d,
                                     unsigned long long a,
                                     unsigned long long b) {
    asm("fma.rn.f32x2 %0, %1, %2, %0;" : "+l"(d) : "l"(a), "l"(b));
}
__device__ __forceinline__ float sum2(unsigned long long v) {
    float lo, hi;
    asm("mov.b64 {%0, %1}, %2;" : "=f"(lo), "=f"(hi) : "l"(v));
    return lo + hi;
}
__device__ __forceinline__ unsigned long long pack2(float lo, float hi) {
    unsigned long long v;
    asm("mov.b64 %0, {%1, %2};" : "=l"(v) : "f"(lo), "f"(hi));
    return v;
}
__device__ __forceinline__ float sigf(float x) {
    return 0.5f + 0.5f * tanhf(0.5f * x);
}

__global__ void __launch_bounds__(NTHR, 1) gru_fused_v3(
    const float* __restrict__ history,  // [B][T][D]
    const float* __restrict__ W_ih,     // [3H][D]
    const float* __restrict__ W_hh,     // [3H][H]
    const float* __restrict__ b_ih,     // [3H]
    const float* __restrict__ b_hh,     // [3H]
    const float* __restrict__ h0,       // [H]
    float* __restrict__ out)            // [B][H]
{
    extern __shared__ float smem[];
    float* sW  = smem;
    float* sH  = smem + OFF_H;    // [2][NB][HH]
    float* sHr = smem + OFF_HR;   // [2][NB][64]
    float* sX  = smem + OFF_X;    // [2][NB][DP]

    const int tid  = threadIdx.x;
    const int b0   = blockIdx.x * NB;
    const int lane = tid & 31;
    const int wid  = tid >> 5;
    const int half = (lane >> 4);        // 0: k<64, 1: k>=64
    const int u    = wid * 16 + (lane & 15);   // hidden unit (gate warps)

    // ---- stage W_hh k-chunk-major ----
    for (int idx = tid; idx < GG * HH; idx += NTHR) {
        int j = idx >> 7, k = idx & 127;
        sW[((k >> 2) * GG + j) * 4 + (k & 3)] = W_hh[idx];
    }
    // ---- h(0): main + replica ----
    for (int idx = tid; idx < NB * HH; idx += NTHR) {
        float v = h0[idx & 127];
        sH[idx] = v;
        int k = idx & 127, nb = idx >> 7;
        if (k >= 64) sHr[nb * 64 + (k - 64)] = v;
    }
    // ---- zero x pads (both buffers) ----
    if (tid < 16) {
        int buf = tid >> 3, nb = (tid >> 1) & 3, d = DD + (tid & 1);
        sX[buf * (NB * DP) + nb * DP + d] = 0.f;
    }
    // ---- x(0) ----
    for (int idx = tid; idx < NB * DD; idx += NTHR) {
        int nb = idx / DD, d = idx - nb * DD;
        sX[nb * DP + d] = history[(size_t)(b0 + nb) * (TT * DD) + d];
    }

    // ---- per-thread W_ih half-rows (24 k each, pads zero) + biases ----
    unsigned long long wih[3][12];
    float bi[3], bh[3];
    if (tid < NGATE) {
        #pragma unroll
        for (int g = 0; g < 3; g++) {
            const int j = g * HH + u;
            bi[g] = b_ih[j];
            bh[g] = b_hh[j];
            #pragma unroll
            for (int p = 0; p < 12; p++) {
                int k0 = half * 24 + 2 * p;
                float f0 = (k0     < DD) ? W_ih[j * DD + k0]     : 0.f;
                float f1 = (k0 + 1 < DD) ? W_ih[j * DD + k0 + 1] : 0.f;
                wih[g][p] = pack2(f0, f1);
            }
        }
    }

    // per-thread bases (gate threads)
    const ulonglong2* wbase = (const ulonglong2*)sW + (half * 16) * GG + u;

    __syncthreads();

    for (int t = 0; t < TT; t++) {
        const int cur = t & 1, nxt = cur ^ 1;

        if (tid < NGATE) {
            // h pointers: half 0 reads main, half 1 reads replica
            const float* hp0;
            int hstride;
            if (half == 0) { hp0 = sH + cur * (NB * HH); hstride = HH; }
            else           { hp0 = sHr + cur * (NB * 64); hstride = 64; }
            const float* hp[NB] = { hp0, hp0 + hstride, hp0 + 2 * hstride,
                                    hp0 + 3 * hstride };
            const float* xq = sX + cur * (NB * DP) + half * 24;

            unsigned long long ah[3][NB], ai[3][NB];
            #pragma unroll
            for (int g = 0; g < 3; g++)
                #pragma unroll
                for (int nb = 0; nb < NB; nb++) { ah[g][nb] = 0ull; ai[g][nb] = 0ull; }

            // ---- W_hh partial dot: 16 local k-chunks of 4 ----
            #pragma unroll 8
            for (int kc = 0; kc < 16; kc++) {
                ulonglong2 w0 = wbase[kc * GG];
                ulonglong2 w1 = wbase[kc * GG + HH];
                ulonglong2 w2 = wbase[kc * GG + 2 * HH];
                ulonglong2 hA = *(const ulonglong2*)(hp[0] + kc * 4);
                ulonglong2 hB = *(const ulonglong2*)(hp[1] + kc * 4);
                ulonglong2 hC = *(const ulonglong2*)(hp[2] + kc * 4);
                ulonglong2 hD = *(const ulonglong2*)(hp[3] + kc * 4);
                fma2(ah[0][0], w0.x, hA.x); fma2(ah[0][0], w0.y, hA.y);
                fma2(ah[0][1], w0.x, hB.x); fma2(ah[0][1], w0.y, hB.y);
                fma2(ah[0][2], w0.x, hC.x); fma2(ah[0][2], w0.y, hC.y);
                fma2(ah[0][3], w0.x, hD.x); fma2(ah[0][3], w0.y, hD.y);
                fma2(ah[1][0], w1.x, hA.x); fma2(ah[1][0], w1.y, hA.y);
                fma2(ah[1][1], w1.x, hB.x); fma2(ah[1][1], w1.y, hB.y);
                fma2(ah[1][2], w1.x, hC.x); fma2(ah[1][2], w1.y, hC.y);
                fma2(ah[1][3], w1.x, hD.x); fma2(ah[1][3], w1.y, hD.y);
                fma2(ah[2][0], w2.x, hA.x); fma2(ah[2][0], w2.y, hA.y);
                fma2(ah[2][1], w2.x, hB.x); fma2(ah[2][1], w2.y, hB.y);
                fma2(ah[2][2], w2.x, hC.x); fma2(ah[2][2], w2.y, hC.y);
                fma2(ah[2][3], w2.x, hD.x); fma2(ah[2][3], w2.y, hD.y);
            }
            // ---- W_ih partial dot: 6 local x-chunks of 4 ----
            #pragma unroll
            for (int q = 0; q < 6; q++) {
                ulonglong2 xA = *(const ulonglong2*)(xq + 0 * DP + 4 * q);
                ulonglong2 xB = *(const ulonglong2*)(xq + 1 * DP + 4 * q);
                ulonglong2 xC = *(const ulonglong2*)(xq + 2 * DP + 4 * q);
                ulonglong2 xD = *(const ulonglong2*)(xq + 3 * DP + 4 * q);
                #pragma unroll
                for (int g = 0; g < 3; g++) {
                    unsigned long long wa = wih[g][2 * q], wb = wih[g][2 * q + 1];
                    fma2(ai[g][0], wa, xA.x); fma2(ai[g][0], wb, xA.y);
                    fma2(ai[g][1], wa, xB.x); fma2(ai[g][1], wb, xB.y);
                    fma2(ai[g][2], wa, xC.x); fma2(ai[g][2], wb, xC.y);
                    fma2(ai[g][3], wa, xD.x); fma2(ai[g][3], wb, xD.y);
                }
            }

            // ---- combine halves via shuffle, then finish on lanes 0-15 ----
            float pr[NB], pz[NB], pxn[NB], pgn[NB];
            #pragma unroll
            for (int nb = 0; nb < NB; nb++) {
                pr[nb]  = sum2(ah[0][nb]) + sum2(ai[0][nb]);
                pz[nb]  = sum2(ah[1][nb]) + sum2(ai[1][nb]);
                pgn[nb] = sum2(ah[2][nb]);
                pxn[nb] = sum2(ai[2][nb]);
            }
            #pragma unroll
            for (int nb = 0; nb < NB; nb++) {
                pr[nb]  += __shfl_down_sync(0xffffffffu, pr[nb],  16);
                pz[nb]  += __shfl_down_sync(0xffffffffu, pz[nb],  16);
                pgn[nb] += __shfl_down_sync(0xffffffffu, pgn[nb], 16);
                pxn[nb] += __shfl_down_sync(0xffffffffu, pxn[nb], 16);
            }

            if (half == 0) {
                const float* hc = sH + cur * (NB * HH);
                float* hn  = sH  + nxt * (NB * HH);
                float* hnr = sHr + nxt * (NB * 64);
                #pragma unroll
                for (int nb = 0; nb < NB; nb++) {
                    float r = sigf(pr[nb] + bi[0] + bh[0]);
                    float z = sigf(pz[nb] + bi[1] + bh[1]);
                    float n = tanhf(pxn[nb] + bi[2] + r * (pgn[nb] + bh[2]));
                    float hold = hc[nb * HH + u];
                    float hv = n + z * (hold - n);
                    hn[nb * HH + u] = hv;
                    if (u >= 64) hnr[nb * 64 + (u - 64)] = hv;
                    if (t == TT - 1)
                        out[(size_t)(b0 + nb) * HH + u] = hv;
                }
            }
        } else {
            // ---- aux: prefetch x(t+1) ----
            if (t + 1 < TT) {
                const int a = tid - NGATE;   // 0..63
                #pragma unroll
                for (int r = 0; r < 3; r++) {
                    int idx = a + r * 64;
                    if (idx < NB * DD) {
                        int nb = idx / DD, d = idx - nb * DD;
                        sX[nxt * (NB * DP) + nb * DP + d] =
                            history[(size_t)(b0 + nb) * (TT * DD) + (t + 1) * DD + d];
                    }
                }
            }
        }

        __syncthreads();   // h(t+1) (both copies) + x(t+1) visible
    }
}

extern "C" void kernel_launch(void* const* d_in, const int* in_sizes, int n_in,
                              void* d_out, int out_size) {
    const float* history = (const float*)d_in[0];
    const float* W_ih    = (const float*)d_in[1];
    const float* W_hh    = (const float*)d_in[2];
    const float* b_ih    = (const float*)d_in[3];
    const float* b_hh    = (const float*)d_in[4];
    const float* h0      = (const float*)d_in[5];
    float* out = (float*)d_out;

    cudaFuncSetAttribute(gru_fused_v3,
                         cudaFuncAttributeMaxDynamicSharedMemorySize, SMEM_BYTES);
    gru_fused_v3<<<NCTA, NTHR, SMEM_BYTES>>>(history, W_ih, W_hh,
                                             b_ih, b_hh, h0, out);
}